// round 16
// baseline (speedup 1.0000x reference)
#include <cuda_runtime.h>
#include <cuda_bf16.h>

#define MAX_NODES 100000
#define D 128
#define TILE_M 128
#define CAP 96                            // bucket capacity per node

// ---------------------------------------------------------------------------
// Device scratch
// ---------------------------------------------------------------------------
__device__ float g_comb[(size_t)MAX_NODES * D];
__device__ int   g_cnt[MAX_NODES];
__device__ __align__(16) uint2 g_bucket[(size_t)MAX_NODES * CAP]; // {col, val}
// B-fragment images for mma.sync m16n8k16 (bf16): W1hi, W1lo, W2hi, W2lo.
// Layout: [s(8)][g(2)][t(8)][lane(32)] uint2 — lane fastest => coalesced LDG.64
__device__ __align__(16) uint2 g_wfrag[4 * 4096];

// ---------------------------------------------------------------------------
// Kernel 1: zero bucket counters
// ---------------------------------------------------------------------------
__global__ void zero_cnt(int n_nodes) {
    int i = blockIdx.x * blockDim.x + threadIdx.x;
    if (i < n_nodes) g_cnt[i] = 0;
}

// ---------------------------------------------------------------------------
// Kernel 2: fill buckets, 4 edges/thread (vector loads, 4 indep. chains)
// ---------------------------------------------------------------------------
__global__ void __launch_bounds__(256) fill_edges(
    const int* __restrict__ row_idx, const int* __restrict__ col_idx,
    const float* __restrict__ val, int n_edges)
{
    int e0 = (blockIdx.x * blockDim.x + threadIdx.x) * 4;
    if (e0 + 3 < n_edges) {
        int4   r4 = __ldg(reinterpret_cast<const int4*>(row_idx + e0));
        int4   c4 = __ldg(reinterpret_cast<const int4*>(col_idx + e0));
        float4 v4 = __ldg(reinterpret_cast<const float4*>(val + e0));
        int p0 = atomicAdd(&g_cnt[r4.x], 1);
        int p1 = atomicAdd(&g_cnt[r4.y], 1);
        int p2 = atomicAdd(&g_cnt[r4.z], 1);
        int p3 = atomicAdd(&g_cnt[r4.w], 1);
        if (p0 < CAP) g_bucket[(size_t)r4.x * CAP + p0] =
            make_uint2((unsigned)c4.x, __float_as_uint(v4.x));
        if (p1 < CAP) g_bucket[(size_t)r4.y * CAP + p1] =
            make_uint2((unsigned)c4.y, __float_as_uint(v4.y));
        if (p2 < CAP) g_bucket[(size_t)r4.z * CAP + p2] =
            make_uint2((unsigned)c4.z, __float_as_uint(v4.z));
        if (p3 < CAP) g_bucket[(size_t)r4.w * CAP + p3] =
            make_uint2((unsigned)c4.w, __float_as_uint(v4.w));
    } else {
        for (int e = e0; e < n_edges; e++) {
            int r = __ldg(row_idx + e);
            int c = __ldg(col_idx + e);
            float v = __ldg(val + e);
            int p = atomicAdd(&g_cnt[r], 1);
            if (p < CAP) g_bucket[(size_t)r * CAP + p] =
                make_uint2((unsigned)c, __float_as_uint(v));
        }
    }
}

// ---------------------------------------------------------------------------
// Kernel 3: gather — EXACT R9/R13 configuration (proven 58.5us).
// ---------------------------------------------------------------------------
__global__ void __launch_bounds__(256) gather_kernel(
    const float* __restrict__ feat, int n_nodes)
{
    int node = blockIdx.x * 8 + (threadIdx.x >> 5);
    int lane = threadIdx.x & 31;
    if (node >= n_nodes) return;

    int deg = min(__ldg(g_cnt + node), CAP);

    // residual (1+eps)*feat, eps = 0
    float4 acc = __ldg(reinterpret_cast<const float4*>(feat) +
                       (size_t)node * 32 + lane);

    const uint2* bucket = g_bucket + (size_t)node * CAP;
    for (int base = 0; base < deg; base += 32) {
        int m = min(32, deg - base);
        int   cc = 0;
        float vv = 0.f;
        if (lane < m) {
            uint2 ev = __ldg(bucket + base + lane);
            cc = (int)ev.x;
            vv = __uint_as_float(ev.y);
        }
        int j = 0;
        for (; j + 4 <= m; j += 4) {
            int   c0 = __shfl_sync(0xFFFFFFFFu, cc, j);
            int   c1 = __shfl_sync(0xFFFFFFFFu, cc, j + 1);
            int   c2 = __shfl_sync(0xFFFFFFFFu, cc, j + 2);
            int   c3 = __shfl_sync(0xFFFFFFFFu, cc, j + 3);
            float v0 = __shfl_sync(0xFFFFFFFFu, vv, j);
            float v1 = __shfl_sync(0xFFFFFFFFu, vv, j + 1);
            float v2 = __shfl_sync(0xFFFFFFFFu, vv, j + 2);
            float v3 = __shfl_sync(0xFFFFFFFFu, vv, j + 3);
            float4 f0 = __ldg(reinterpret_cast<const float4*>(feat) + (size_t)c0 * 32 + lane);
            float4 f1 = __ldg(reinterpret_cast<const float4*>(feat) + (size_t)c1 * 32 + lane);
            float4 f2 = __ldg(reinterpret_cast<const float4*>(feat) + (size_t)c2 * 32 + lane);
            float4 f3 = __ldg(reinterpret_cast<const float4*>(feat) + (size_t)c3 * 32 + lane);
            acc.x = fmaf(v0, f0.x, acc.x); acc.y = fmaf(v0, f0.y, acc.y);
            acc.z = fmaf(v0, f0.z, acc.z); acc.w = fmaf(v0, f0.w, acc.w);
            acc.x = fmaf(v1, f1.x, acc.x); acc.y = fmaf(v1, f1.y, acc.y);
            acc.z = fmaf(v1, f1.z, acc.z); acc.w = fmaf(v1, f1.w, acc.w);
            acc.x = fmaf(v2, f2.x, acc.x); acc.y = fmaf(v2, f2.y, acc.y);
            acc.z = fmaf(v2, f2.z, acc.z); acc.w = fmaf(v2, f2.w, acc.w);
            acc.x = fmaf(v3, f3.x, acc.x); acc.y = fmaf(v3, f3.y, acc.y);
            acc.z = fmaf(v3, f3.z, acc.z); acc.w = fmaf(v3, f3.w, acc.w);
        }
        for (; j < m; j++) {
            int   c0 = __shfl_sync(0xFFFFFFFFu, cc, j);
            float v0 = __shfl_sync(0xFFFFFFFFu, vv, j);
            float4 f0 = __ldg(reinterpret_cast<const float4*>(feat) + (size_t)c0 * 32 + lane);
            acc.x = fmaf(v0, f0.x, acc.x); acc.y = fmaf(v0, f0.y, acc.y);
            acc.z = fmaf(v0, f0.z, acc.z); acc.w = fmaf(v0, f0.w, acc.w);
        }
    }

    reinterpret_cast<float4*>(g_comb)[(size_t)node * 32 + lane] = acc;
}

// ---------------------------------------------------------------------------
// bf16 split helpers
// ---------------------------------------------------------------------------
__device__ __forceinline__ void split1(float a, unsigned short& h, unsigned short& l) {
    __nv_bfloat16 hb = __float2bfloat16(a);
    __nv_bfloat16 lb = __float2bfloat16(a - __bfloat162float(hb));
    h = __bfloat16_as_ushort(hb);
    l = __bfloat16_as_ushort(lb);
}
__device__ __forceinline__ void split2(float a, float b, unsigned& hp, unsigned& lp) {
    unsigned short ha, la, hb, lb;
    split1(a, ha, la);
    split1(b, hb, lb);
    hp = (unsigned)ha | ((unsigned)hb << 16);
    lp = (unsigned)la | ((unsigned)lb << 16);
}

__device__ __forceinline__ unsigned smem_u32(const void* p) {
    unsigned a;
    asm("{ .reg .u64 t; cvta.to.shared.u64 t, %1; cvt.u32.u64 %0, t; }"
        : "=r"(a) : "l"(p));
    return a;
}

// ---------------------------------------------------------------------------
// Kernel 4: weight prep -> B fragments (hi/lo), layout [s][g][t][lane].
// ---------------------------------------------------------------------------
__global__ void wprep(const float* __restrict__ W1, const float* __restrict__ W2) {
    int idx = blockIdx.x * 256 + threadIdx.x;         // 0..8191
    if (idx >= 8192) return;
    int which = idx >> 12;                            // 0:W1 1:W2
    int f = idx & 4095;                               // ((s*2+g)*8+t)*32 + lane
    int lane = f & 31;
    int t = (f >> 5) & 7;
    int g = (f >> 8) & 1;
    int s = f >> 9;
    int n  = g * 64 + t * 8 + (lane >> 2);
    int k0 = s * 16 + (lane & 3) * 2;

    const float* W = which ? W2 : W1;
    float v00 = __ldg(W + k0 * D + n);
    float v01 = __ldg(W + (k0 + 1) * D + n);
    float v10 = __ldg(W + (k0 + 8) * D + n);
    float v11 = __ldg(W + (k0 + 9) * D + n);

    unsigned h0, l0, h1, l1;
    split2(v00, v01, h0, l0);
    split2(v10, v11, h1, l1);

    uint2* hi = g_wfrag + which * 8192;
    uint2* lo = hi + 4096;
    hi[f] = make_uint2(h0, h1);
    lo[f] = make_uint2(l0, l1);
}

// ---------------------------------------------------------------------------
// Kernel 5: fused MLP — 256 threads / 8 warps, block tile 128 x 128.
// Warp tile 32 rows x 64 cols (2 m-tiles x 8 n-tiles): each B-fragment
// load feeds 32 MMAs -> W L1 traffic halved vs 16-row warp tile.
// ---------------------------------------------------------------------------
#define A_STRIDE 272                      // 128 bf16 + 8 pad (conflict-free)
#define AH_OFF   0
#define AL_OFF   34816                    // 128*272
#define B1_OFF   69632
#define B2_OFF   70144
#define SMEM_TOT 70656

__device__ __forceinline__ void ldmat4(unsigned& a0, unsigned& a1,
                                       unsigned& a2, unsigned& a3, unsigned addr) {
    asm volatile("ldmatrix.sync.aligned.m8n8.x4.shared.b16 {%0,%1,%2,%3}, [%4];"
                 : "=r"(a0), "=r"(a1), "=r"(a2), "=r"(a3) : "r"(addr));
}

__device__ __forceinline__ void mma_bf16(float* c,
                                         unsigned a0, unsigned a1, unsigned a2,
                                         unsigned a3, unsigned b0, unsigned b1) {
    asm volatile(
        "mma.sync.aligned.m16n8k16.row.col.f32.bf16.bf16.f32 "
        "{%0,%1,%2,%3}, {%4,%5,%6,%7}, {%8,%9}, {%0,%1,%2,%3};"
        : "+f"(c[0]), "+f"(c[1]), "+f"(c[2]), "+f"(c[3])
        : "r"(a0), "r"(a1), "r"(a2), "r"(a3), "r"(b0), "r"(b1));
}

__device__ __forceinline__ void ldb(uint2 b[8], const uint2* __restrict__ w,
                                    int s, int g, int lane) {
    const uint2* p = w + ((size_t)(s * 2 + g) * 8) * 32 + lane;
    #pragma unroll
    for (int t = 0; t < 8; t++) b[t] = __ldg(p + t * 32);
}

// GEMM with fused 3-pass split over 2 m-tiles:
// acc[m] += Ahi_m*Bhi + Alo_m*Bhi + Ahi_m*Blo
__device__ __forceinline__ void gemm3(unsigned aH0, unsigned aL0,
                                      const uint2* __restrict__ whi,
                                      const uint2* __restrict__ wlo,
                                      float acc[2][8][4], int g, int lane)
{
    const unsigned khalf = (lane >> 4) * 16;
    uint2 bh[8], bl[8];
    ldb(bh, whi, 0, g, lane);
    #pragma unroll
    for (int s = 0; s < 8; s++) {
        const unsigned koff = s * 32 + khalf;
        unsigned ah[2][4], al[2][4];
        ldmat4(ah[0][0], ah[0][1], ah[0][2], ah[0][3], aH0 + koff);
        ldmat4(ah[1][0], ah[1][1], ah[1][2], ah[1][3], aH0 + 16 * A_STRIDE + koff);
        ldmat4(al[0][0], al[0][1], al[0][2], al[0][3], aL0 + koff);
        ldmat4(al[1][0], al[1][1], al[1][2], al[1][3], aL0 + 16 * A_STRIDE + koff);

        ldb(bl, wlo, s, g, lane);             // shadowed by bh MMAs

        #pragma unroll
        for (int t = 0; t < 8; t++) {
            mma_bf16(acc[0][t], ah[0][0], ah[0][1], ah[0][2], ah[0][3], bh[t].x, bh[t].y);
            mma_bf16(acc[1][t], ah[1][0], ah[1][1], ah[1][2], ah[1][3], bh[t].x, bh[t].y);
        }
        #pragma unroll
        for (int t = 0; t < 8; t++) {
            mma_bf16(acc[0][t], al[0][0], al[0][1], al[0][2], al[0][3], bh[t].x, bh[t].y);
            mma_bf16(acc[1][t], al[1][0], al[1][1], al[1][2], al[1][3], bh[t].x, bh[t].y);
        }

        if (s < 7)
            ldb(bh, whi, s + 1, g, lane);     // shadowed by bl MMAs

        #pragma unroll
        for (int t = 0; t < 8; t++) {
            mma_bf16(acc[0][t], ah[0][0], ah[0][1], ah[0][2], ah[0][3], bl[t].x, bl[t].y);
            mma_bf16(acc[1][t], ah[1][0], ah[1][1], ah[1][2], ah[1][3], bl[t].x, bl[t].y);
        }
    }
}

__global__ void __launch_bounds__(256, 2) fused_mlp_mma(
    const float* __restrict__ b1, const float* __restrict__ b2,
    float* __restrict__ out, int n_nodes)
{
    extern __shared__ __align__(16) unsigned char smem[];
    const unsigned sb = smem_u32(smem);
    const int tid  = threadIdx.x;
    const int wid  = tid >> 5;
    const int lane = tid & 31;
    const int rowg = wid >> 1;                 // 0..3 (32 rows each)
    const int g    = wid & 1;                  // col group 0/1 (64 cols)
    const int node0 = blockIdx.x * TILE_M;
    const int r0 = rowg * 32 + (lane >> 2);    // acc row (m-tile 0)
    const int cb = (lane & 3) * 2;             // col pair within n-tile

    if (tid < 128) {
        ((float*)(smem + B1_OFF))[tid] = __ldg(b1 + tid);
        ((float*)(smem + B2_OFF))[tid] = __ldg(b2 + tid);
    }

    // ---- load X tile (128 rows x 32 float4), split to A images ----
    #pragma unroll
    for (int i = 0; i < 16; i++) {
        int idx = tid + i * 256;
        int row = idx >> 5, c4 = idx & 31;
        int gn = node0 + row;
        float4 v = make_float4(0.f, 0.f, 0.f, 0.f);
        if (gn < n_nodes)
            v = __ldg(reinterpret_cast<const float4*>(g_comb) + (size_t)gn * 32 + c4);
        unsigned h01, l01, h23, l23;
        split2(v.x, v.y, h01, l01);
        split2(v.z, v.w, h23, l23);
        unsigned off = row * A_STRIDE + c4 * 8;
        *reinterpret_cast<uint2*>(smem + AH_OFF + off) = make_uint2(h01, h23);
        *reinterpret_cast<uint2*>(smem + AL_OFF + off) = make_uint2(l01, l23);
    }
    __syncthreads();

    const unsigned arow = (rowg * 32 + (lane & 15)) * A_STRIDE;
    const unsigned aH = sb + AH_OFF + arow;
    const unsigned aL = sb + AL_OFF + arow;

    float acc[2][8][4];

    // ===== GEMM1 (W1) =====
    #pragma unroll
    for (int m = 0; m < 2; m++)
        #pragma unroll
        for (int t = 0; t < 8; t++)
            acc[m][t][0] = acc[m][t][1] = acc[m][t][2] = acc[m][t][3] = 0.f;
    gemm3(aH, aL, g_wfrag, g_wfrag + 4096, acc, g, lane);
    __syncthreads();

    // ---- epilogue1: +b1, relu, re-split into A images ----
    #pragma unroll
    for (int m = 0; m < 2; m++) {
        const int rA = r0 + m * 16;
        #pragma unroll
        for (int t = 0; t < 8; t++) {
            int c = (g * 8 + t) * 8 + cb;
            float bb0 = ((float*)(smem + B1_OFF))[c];
            float bb1 = ((float*)(smem + B1_OFF))[c + 1];
            float h0 = fmaxf(acc[m][t][0] + bb0, 0.f);
            float h1 = fmaxf(acc[m][t][1] + bb1, 0.f);
            float h2 = fmaxf(acc[m][t][2] + bb0, 0.f);
            float h3 = fmaxf(acc[m][t][3] + bb1, 0.f);
            unsigned hp, lp;
            unsigned off0 = rA * A_STRIDE + c * 2;
            unsigned off1 = (rA + 8) * A_STRIDE + c * 2;
            split2(h0, h1, hp, lp);
            *reinterpret_cast<unsigned*>(smem + AH_OFF + off0) = hp;
            *reinterpret_cast<unsigned*>(smem + AL_OFF + off0) = lp;
            split2(h2, h3, hp, lp);
            *reinterpret_cast<unsigned*>(smem + AH_OFF + off1) = hp;
            *reinterpret_cast<unsigned*>(smem + AL_OFF + off1) = lp;
        }
    }
    __syncthreads();

    // ===== GEMM2 (W2) =====
    #pragma unroll
    for (int m = 0; m < 2; m++)
        #pragma unroll
        for (int t = 0; t < 8; t++)
            acc[m][t][0] = acc[m][t][1] = acc[m][t][2] = acc[m][t][3] = 0.f;
    gemm3(aH, aL, g_wfrag + 8192, g_wfrag + 12288, acc, g, lane);

    // ---- epilogue2: +b2 -> out ----
    #pragma unroll
    for (int m = 0; m < 2; m++) {
        const int gnA = node0 + r0 + m * 16;
        const int gnB = gnA + 8;
        #pragma unroll
        for (int t = 0; t < 8; t++) {
            int c = (g * 8 + t) * 8 + cb;
            float bb0 = ((float*)(smem + B2_OFF))[c];
            float bb1 = ((float*)(smem + B2_OFF))[c + 1];
            if (gnA < n_nodes) {
                float2 o = make_float2(acc[m][t][0] + bb0, acc[m][t][1] + bb1);
                *reinterpret_cast<float2*>(out + (size_t)gnA * D + c) = o;
            }
            if (gnB < n_nodes) {
                float2 o = make_float2(acc[m][t][2] + bb0, acc[m][t][3] + bb1);
                *reinterpret_cast<float2*>(out + (size_t)gnB * D + c) = o;
            }
        }
    }
}

// ---------------------------------------------------------------------------
// Launch
// ---------------------------------------------------------------------------
extern "C" void kernel_launch(void* const* d_in, const int* in_sizes, int n_in,
                              void* d_out, int out_size)
{
    const int*   indices  = (const int*)d_in[0];
    const float* values   = (const float*)d_in[1];
    const float* features = (const float*)d_in[2];
    const float* W1       = (const float*)d_in[3];
    const float* b1       = (const float*)d_in[4];
    const float* W2       = (const float*)d_in[5];
    const float* b2       = (const float*)d_in[6];
    float*       out      = (float*)d_out;

    const int n_edges = in_sizes[1];
    const int n_nodes = in_sizes[2] / D;
    const int* row_idx = indices;
    const int* col_idx = indices + n_edges;

    cudaFuncSetAttribute(fused_mlp_mma,
                         cudaFuncAttributeMaxDynamicSharedMemorySize, SMEM_TOT);

    // 1) zero counters
    zero_cnt<<<(n_nodes + 255) / 256, 256>>>(n_nodes);
    // 2) fill per-node buckets (4 edges/thread, vectorized)
    fill_edges<<<(n_edges / 4 + 255) / 256, 256>>>(row_idx, col_idx, values,
                                                   n_edges);
    // 3) weight split -> fragment images
    wprep<<<32, 256>>>(W1, W2);
    // 4) gather: combined = feat + A*feat  (exact R9/R13 config)
    gather_kernel<<<(n_nodes + 7) / 8, 256>>>(features, n_nodes);
    // 5) tensor-core MLP (block tile 128x128, warp tile 32x64)
    fused_mlp_mma<<<(n_nodes + TILE_M - 1) / TILE_M, 256, SMEM_TOT>>>(
        b1, b2, out, n_nodes);
}

// round 17
// speedup vs baseline: 1.0854x; 1.0854x over previous
#include <cuda_runtime.h>
#include <cuda_bf16.h>

#define MAX_NODES 100000
#define D 128
#define TILE_M 64
#define CAP 96                            // bucket capacity per node

// ---------------------------------------------------------------------------
// Device scratch
// ---------------------------------------------------------------------------
__device__ float g_comb[(size_t)MAX_NODES * D];
__device__ int   g_cnt[MAX_NODES];
__device__ __align__(16) uint2 g_bucket[(size_t)MAX_NODES * CAP]; // {col, val}
// tf32 B-fragment images for mma.sync m16n8k8: W1, W2.
// Layout: [s(16)][g(2)][t(8)][lane(32)] uint2 {b0,b1} — lane fastest.
__device__ __align__(16) uint2 g_wfrag[2 * 8192];

// ---------------------------------------------------------------------------
// Kernel 1: zero bucket counters
// ---------------------------------------------------------------------------
__global__ void zero_cnt(int n_nodes) {
    int i = blockIdx.x * blockDim.x + threadIdx.x;
    if (i < n_nodes) g_cnt[i] = 0;
}

// ---------------------------------------------------------------------------
// Kernel 2: fill buckets, 4 edges/thread (vector loads, 4 indep. chains)
// ---------------------------------------------------------------------------
__global__ void __launch_bounds__(256) fill_edges(
    const int* __restrict__ row_idx, const int* __restrict__ col_idx,
    const float* __restrict__ val, int n_edges)
{
    int e0 = (blockIdx.x * blockDim.x + threadIdx.x) * 4;
    if (e0 + 3 < n_edges) {
        int4   r4 = __ldg(reinterpret_cast<const int4*>(row_idx + e0));
        int4   c4 = __ldg(reinterpret_cast<const int4*>(col_idx + e0));
        float4 v4 = __ldg(reinterpret_cast<const float4*>(val + e0));
        int p0 = atomicAdd(&g_cnt[r4.x], 1);
        int p1 = atomicAdd(&g_cnt[r4.y], 1);
        int p2 = atomicAdd(&g_cnt[r4.z], 1);
        int p3 = atomicAdd(&g_cnt[r4.w], 1);
        if (p0 < CAP) g_bucket[(size_t)r4.x * CAP + p0] =
            make_uint2((unsigned)c4.x, __float_as_uint(v4.x));
        if (p1 < CAP) g_bucket[(size_t)r4.y * CAP + p1] =
            make_uint2((unsigned)c4.y, __float_as_uint(v4.y));
        if (p2 < CAP) g_bucket[(size_t)r4.z * CAP + p2] =
            make_uint2((unsigned)c4.z, __float_as_uint(v4.z));
        if (p3 < CAP) g_bucket[(size_t)r4.w * CAP + p3] =
            make_uint2((unsigned)c4.w, __float_as_uint(v4.w));
    } else {
        for (int e = e0; e < n_edges; e++) {
            int r = __ldg(row_idx + e);
            int c = __ldg(col_idx + e);
            float v = __ldg(val + e);
            int p = atomicAdd(&g_cnt[r], 1);
            if (p < CAP) g_bucket[(size_t)r * CAP + p] =
                make_uint2((unsigned)c, __float_as_uint(v));
        }
    }
}

// ---------------------------------------------------------------------------
// Kernel 3: gather — EXACT R9/R13 configuration (proven 58.5us).
// ---------------------------------------------------------------------------
__global__ void __launch_bounds__(256) gather_kernel(
    const float* __restrict__ feat, int n_nodes)
{
    int node = blockIdx.x * 8 + (threadIdx.x >> 5);
    int lane = threadIdx.x & 31;
    if (node >= n_nodes) return;

    int deg = min(__ldg(g_cnt + node), CAP);

    // residual (1+eps)*feat, eps = 0
    float4 acc = __ldg(reinterpret_cast<const float4*>(feat) +
                       (size_t)node * 32 + lane);

    const uint2* bucket = g_bucket + (size_t)node * CAP;
    for (int base = 0; base < deg; base += 32) {
        int m = min(32, deg - base);
        int   cc = 0;
        float vv = 0.f;
        if (lane < m) {
            uint2 ev = __ldg(bucket + base + lane);
            cc = (int)ev.x;
            vv = __uint_as_float(ev.y);
        }
        int j = 0;
        for (; j + 4 <= m; j += 4) {
            int   c0 = __shfl_sync(0xFFFFFFFFu, cc, j);
            int   c1 = __shfl_sync(0xFFFFFFFFu, cc, j + 1);
            int   c2 = __shfl_sync(0xFFFFFFFFu, cc, j + 2);
            int   c3 = __shfl_sync(0xFFFFFFFFu, cc, j + 3);
            float v0 = __shfl_sync(0xFFFFFFFFu, vv, j);
            float v1 = __shfl_sync(0xFFFFFFFFu, vv, j + 1);
            float v2 = __shfl_sync(0xFFFFFFFFu, vv, j + 2);
            float v3 = __shfl_sync(0xFFFFFFFFu, vv, j + 3);
            float4 f0 = __ldg(reinterpret_cast<const float4*>(feat) + (size_t)c0 * 32 + lane);
            float4 f1 = __ldg(reinterpret_cast<const float4*>(feat) + (size_t)c1 * 32 + lane);
            float4 f2 = __ldg(reinterpret_cast<const float4*>(feat) + (size_t)c2 * 32 + lane);
            float4 f3 = __ldg(reinterpret_cast<const float4*>(feat) + (size_t)c3 * 32 + lane);
            acc.x = fmaf(v0, f0.x, acc.x); acc.y = fmaf(v0, f0.y, acc.y);
            acc.z = fmaf(v0, f0.z, acc.z); acc.w = fmaf(v0, f0.w, acc.w);
            acc.x = fmaf(v1, f1.x, acc.x); acc.y = fmaf(v1, f1.y, acc.y);
            acc.z = fmaf(v1, f1.z, acc.z); acc.w = fmaf(v1, f1.w, acc.w);
            acc.x = fmaf(v2, f2.x, acc.x); acc.y = fmaf(v2, f2.y, acc.y);
            acc.z = fmaf(v2, f2.z, acc.z); acc.w = fmaf(v2, f2.w, acc.w);
            acc.x = fmaf(v3, f3.x, acc.x); acc.y = fmaf(v3, f3.y, acc.y);
            acc.z = fmaf(v3, f3.z, acc.z); acc.w = fmaf(v3, f3.w, acc.w);
        }
        for (; j < m; j++) {
            int   c0 = __shfl_sync(0xFFFFFFFFu, cc, j);
            float v0 = __shfl_sync(0xFFFFFFFFu, vv, j);
            float4 f0 = __ldg(reinterpret_cast<const float4*>(feat) + (size_t)c0 * 32 + lane);
            acc.x = fmaf(v0, f0.x, acc.x); acc.y = fmaf(v0, f0.y, acc.y);
            acc.z = fmaf(v0, f0.z, acc.z); acc.w = fmaf(v0, f0.w, acc.w);
        }
    }

    reinterpret_cast<float4*>(g_comb)[(size_t)node * 32 + lane] = acc;
}

// ---------------------------------------------------------------------------
// helpers
// ---------------------------------------------------------------------------
__device__ __forceinline__ unsigned smem_u32(const void* p) {
    unsigned a;
    asm("{ .reg .u64 t; cvta.to.shared.u64 t, %1; cvt.u32.u64 %0, t; }"
        : "=r"(a) : "l"(p));
    return a;
}
__device__ __forceinline__ unsigned f2tf32(float f) {
    unsigned r;
    asm("cvt.rna.tf32.f32 %0, %1;" : "=r"(r) : "f"(f));
    return r;
}

// ---------------------------------------------------------------------------
// Kernel 4: weight prep -> tf32 B fragments, layout [s(16)][g(2)][t(8)][lane].
// m16n8k8 col-B fragment, lane T, n-tile (g*8+t), k-step s:
//   b0 = W[s*8 + T%4][n],  b1 = W[s*8 + T%4 + 4][n],  n = g*64 + t*8 + T/4
// ---------------------------------------------------------------------------
__global__ void wprep(const float* __restrict__ W1, const float* __restrict__ W2) {
    int idx = blockIdx.x * 256 + threadIdx.x;         // 0..16383
    if (idx >= 16384) return;
    int which = idx >> 13;                            // 0:W1 1:W2
    int f = idx & 8191;                               // ((s*2+g)*8+t)*32 + lane
    int lane = f & 31;
    int t = (f >> 5) & 7;
    int g = (f >> 8) & 1;
    int s = f >> 9;                                   // 0..15
    int n  = g * 64 + t * 8 + (lane >> 2);
    int k0 = s * 8 + (lane & 3);

    const float* W = which ? W2 : W1;
    unsigned b0 = f2tf32(__ldg(W + k0 * D + n));
    unsigned b1 = f2tf32(__ldg(W + (k0 + 4) * D + n));
    g_wfrag[which * 8192 + f] = make_uint2(b0, b1);
}

// ---------------------------------------------------------------------------
// Kernel 5: fused MLP via single-pass tf32 mma.sync (m16n8k8).
// Block: 256 threads / 8 warps, tile 64 nodes x 128 cols.
// Warp (rowg, g): rows rowg*16..+15, cols g*64..+63 (8 n-tiles). acc 8x4.
// A tile fp32 in smem, stride 132 floats (conflict-free for frag LDS).
// ---------------------------------------------------------------------------
#define A_FSTRIDE 132                     // floats per row (128 + 4 pad)
#define A_OFF    0                        // 64*132*4 = 33792 B
#define B1_OFF   33792
#define B2_OFF   34304
#define SMEM_TOT 34816

__device__ __forceinline__ void mma_tf32(float* c,
                                         unsigned a0, unsigned a1, unsigned a2,
                                         unsigned a3, unsigned b0, unsigned b1) {
    asm volatile(
        "mma.sync.aligned.m16n8k8.row.col.f32.tf32.tf32.f32 "
        "{%0,%1,%2,%3}, {%4,%5,%6,%7}, {%8,%9}, {%0,%1,%2,%3};"
        : "+f"(c[0]), "+f"(c[1]), "+f"(c[2]), "+f"(c[3])
        : "r"(a0), "r"(a1), "r"(a2), "r"(a3), "r"(b0), "r"(b1));
}

// Batched, coalesced load of a warp's 8 B-fragments for one (s,g).
__device__ __forceinline__ void ldb(uint2 b[8], const uint2* __restrict__ w,
                                    int s, int g, int lane) {
    const uint2* p = w + ((size_t)(s * 2 + g) * 8) * 32 + lane;
    #pragma unroll
    for (int t = 0; t < 8; t++) b[t] = __ldg(p + t * 32);
}

// Single-pass tf32 GEMM: acc += A x W   (K = 128 via 16 k8 steps)
// B(s+1) prefetched while the 8 MMAs of step s run.
__device__ __forceinline__ void gemm_tf32(const float* aBase,
                                          const uint2* __restrict__ w,
                                          float acc[8][4], int g, int lane)
{
    const int fr = lane >> 2;             // fragment row 0..7
    const int fc = lane & 3;              // fragment col 0..3
    const float* aRow0 = aBase + fr * A_FSTRIDE;
    const float* aRow8 = aBase + (fr + 8) * A_FSTRIDE;

    uint2 b[8], nb[8];
    ldb(b, w, 0, g, lane);
    #pragma unroll
    for (int s = 0; s < 16; s++) {
        const int k = s * 8 + fc;
        unsigned a0 = f2tf32(aRow0[k]);
        unsigned a1 = f2tf32(aRow8[k]);
        unsigned a2 = f2tf32(aRow0[k + 4]);
        unsigned a3 = f2tf32(aRow8[k + 4]);

        if (s < 15) ldb(nb, w, s + 1, g, lane);   // shadowed by MMAs

        #pragma unroll
        for (int t = 0; t < 8; t++)
            mma_tf32(acc[t], a0, a1, a2, a3, b[t].x, b[t].y);

        if (s < 15) {
            #pragma unroll
            for (int t = 0; t < 8; t++) b[t] = nb[t];
        }
    }
}

__global__ void __launch_bounds__(256, 2) fused_mlp_mma(
    const float* __restrict__ b1, const float* __restrict__ b2,
    float* __restrict__ out, int n_nodes)
{
    __shared__ __align__(16) unsigned char smem[SMEM_TOT];
    float* As = reinterpret_cast<float*>(smem + A_OFF);
    const int tid  = threadIdx.x;
    const int wid  = tid >> 5;
    const int lane = tid & 31;
    const int rowg = wid >> 1;                 // 0..3 (16 rows each)
    const int g    = wid & 1;                  // col group 0/1
    const int node0 = blockIdx.x * TILE_M;
    const int r0 = rowg * 16 + (lane >> 2);    // acc row within tile
    const int cb = (lane & 3) * 2;             // col pair within n-tile

    if (tid < 128) {
        ((float*)(smem + B1_OFF))[tid] = __ldg(b1 + tid);
        ((float*)(smem + B2_OFF))[tid] = __ldg(b2 + tid);
    }

    // ---- load X tile (64 rows x 32 float4) into fp32 smem ----
    #pragma unroll
    for (int i = 0; i < 8; i++) {
        int idx = tid + i * 256;
        int row = idx >> 5, c4 = idx & 31;
        int gn = node0 + row;
        float4 v = make_float4(0.f, 0.f, 0.f, 0.f);
        if (gn < n_nodes)
            v = __ldg(reinterpret_cast<const float4*>(g_comb) + (size_t)gn * 32 + c4);
        *reinterpret_cast<float4*>(As + row * A_FSTRIDE + c4 * 4) = v;
    }
    __syncthreads();

    const float* aBase = As + rowg * 16 * A_FSTRIDE;

    float acc[8][4];

    // ===== GEMM1 (W1) =====
    #pragma unroll
    for (int t = 0; t < 8; t++)
        acc[t][0] = acc[t][1] = acc[t][2] = acc[t][3] = 0.f;
    gemm_tf32(aBase, g_wfrag, acc, g, lane);
    __syncthreads();

    // ---- epilogue1: +b1, relu -> back into A tile (fp32) ----
    #pragma unroll
    for (int t = 0; t < 8; t++) {
        int c = (g * 8 + t) * 8 + cb;
        float bb0 = ((float*)(smem + B1_OFF))[c];
        float bb1 = ((float*)(smem + B1_OFF))[c + 1];
        float2 h0 = make_float2(fmaxf(acc[t][0] + bb0, 0.f),
                                fmaxf(acc[t][1] + bb1, 0.f));
        float2 h1 = make_float2(fmaxf(acc[t][2] + bb0, 0.f),
                                fmaxf(acc[t][3] + bb1, 0.f));
        *reinterpret_cast<float2*>(As + r0 * A_FSTRIDE + c)       = h0;
        *reinterpret_cast<float2*>(As + (r0 + 8) * A_FSTRIDE + c) = h1;
    }
    __syncthreads();

    // ===== GEMM2 (W2) =====
    #pragma unroll
    for (int t = 0; t < 8; t++)
        acc[t][0] = acc[t][1] = acc[t][2] = acc[t][3] = 0.f;
    gemm_tf32(aBase, g_wfrag + 8192, acc, g, lane);

    // ---- epilogue2: +b2 -> out ----
    const int gnA = node0 + r0;
    const int gnB = gnA + 8;
    #pragma unroll
    for (int t = 0; t < 8; t++) {
        int c = (g * 8 + t) * 8 + cb;
        float bb0 = ((float*)(smem + B2_OFF))[c];
        float bb1 = ((float*)(smem + B2_OFF))[c + 1];
        if (gnA < n_nodes) {
            float2 o = make_float2(acc[t][0] + bb0, acc[t][1] + bb1);
            *reinterpret_cast<float2*>(out + (size_t)gnA * D + c) = o;
        }
        if (gnB < n_nodes) {
            float2 o = make_float2(acc[t][2] + bb0, acc[t][3] + bb1);
            *reinterpret_cast<float2*>(out + (size_t)gnB * D + c) = o;
        }
    }
}

// ---------------------------------------------------------------------------
// Launch
// ---------------------------------------------------------------------------
extern "C" void kernel_launch(void* const* d_in, const int* in_sizes, int n_in,
                              void* d_out, int out_size)
{
    const int*   indices  = (const int*)d_in[0];
    const float* values   = (const float*)d_in[1];
    const float* features = (const float*)d_in[2];
    const float* W1       = (const float*)d_in[3];
    const float* b1       = (const float*)d_in[4];
    const float* W2       = (const float*)d_in[5];
    const float* b2       = (const float*)d_in[6];
    float*       out      = (float*)d_out;

    const int n_edges = in_sizes[1];
    const int n_nodes = in_sizes[2] / D;
    const int* row_idx = indices;
    const int* col_idx = indices + n_edges;

    // 1) zero counters
    zero_cnt<<<(n_nodes + 255) / 256, 256>>>(n_nodes);
    // 2) fill per-node buckets (4 edges/thread, vectorized)
    fill_edges<<<(n_edges / 4 + 255) / 256, 256>>>(row_idx, col_idx, values,
                                                   n_edges);
    // 3) weight prep -> tf32 fragment images
    wprep<<<64, 256>>>(W1, W2);
    // 4) gather: combined = feat + A*feat  (exact R9/R13 config)
    gather_kernel<<<(n_nodes + 7) / 8, 256>>>(features, n_nodes);
    // 5) tensor-core MLP (single-pass tf32)
    fused_mlp_mma<<<(n_nodes + TILE_M - 1) / TILE_M, 256>>>(
        b1, b2, out, n_nodes);
}